// round 15
// baseline (speedup 1.0000x reference)
#include <cuda_runtime.h>
#include <cuda_fp16.h>
#include <cstdint>

// Problem shapes (fixed by the dataset)
#define B_  4
#define T_  8192
#define D_  512
#define H_  512
#define M_  (B_ * T_)        // 32768 rows

#define NCHUNK 128
#define TC     (T_ / NCHUNK) // 64  (BM = 2*TC: two scan chunks per GEMM CTA)

// Scratch (device globals: allocation-free rule)
// Packed gates: g_cv[m*H+h] = half2{c, v}
__device__ __half2 g_cv[(size_t)M_ * H_];
__device__ float g_sumA[B_ * NCHUNK * H_];
__device__ float g_sumB[B_ * NCHUNK * H_];
__device__ float g_carry[B_ * NCHUNK * H_];

// fp16-rounded operands
__device__ __half g_xh[(size_t)M_ * D_];             // 32 MB
__device__ __half g_wzh[H_ * D_];
__device__ __half g_whh[H_ * D_];

// ---------------------------------------------------------------------------
// GEMM config: CTA tile M=128, N=64, K chunk 32, 8 dual-output warps,
// 3-stage cp.async pipeline (prefetch depth 2), one barrier per chunk.
// ---------------------------------------------------------------------------
#define BM 128
#define BN 64
#define KCH 32
#define NKC (D_ / KCH)       // 16
#define NSTAGE 3

// Row stride 80 = 64B data + 16B pad: multiple of 16 (cp.async/ldmatrix
// alignment); 80*r mod 128, r=0..7 -> {0,80,32,112,64,16,96,48}: conflict-free.
#define RS   80
#define OX_H 0                     // x  : 128 x 80
#define OW0H (OX_H + BM * RS)      // 10240  Wz : 64 x 80
#define OW1H (OW0H + BN * RS)      // 15360  Wh : 64 x 80
#define SSTR (OW1H + BN * RS)      // 20480
#define SMEM_BYTES (NSTAGE * SSTR) // 61440  (>= 32KB epilogue staging)

__device__ __forceinline__ uint32_t smem_u32(const void* p) {
    uint32_t a;
    asm("{ .reg .u64 t; cvta.to.shared.u64 t, %1; cvt.u32.u64 %0, t; }"
        : "=r"(a) : "l"(p));
    return a;
}

#define CP16(dst, src) \
    asm volatile("cp.async.cg.shared.global [%0], [%1], 16;" :: "r"(dst), "l"(src))
#define CP_COMMIT() asm volatile("cp.async.commit_group;" ::: "memory")
#define CP_WAIT(n)  asm volatile("cp.async.wait_group %0;" :: "n"(n) : "memory")

__device__ __forceinline__ void ldsm_x4(uint32_t* r, uint32_t addr) {
    asm volatile("ldmatrix.sync.aligned.m8n8.x4.shared.b16 {%0,%1,%2,%3}, [%4];"
                 : "=r"(r[0]), "=r"(r[1]), "=r"(r[2]), "=r"(r[3]) : "r"(addr));
}

__device__ __forceinline__ void mma_f16(float* d, const uint32_t* a, const uint32_t* b) {
    asm volatile("mma.sync.aligned.m16n8k16.row.col.f32.f16.f16.f32 "
                 "{%0,%1,%2,%3}, {%4,%5,%6,%7}, {%8,%9}, {%0,%1,%2,%3};"
                 : "+f"(d[0]), "+f"(d[1]), "+f"(d[2]), "+f"(d[3])
                 : "r"(a[0]), "r"(a[1]), "r"(a[2]), "r"(a[3]), "r"(b[0]), "r"(b[1]));
}

__device__ __forceinline__ void gate(float k, float a, float& c, float& v) {
    c = 1.f / (1.f + __expf(k));                                 // sigmoid(-k)
    float s = 1.f / (1.f + __expf(-k));                          // sigmoid(k)
    float g = (a >= 0.f) ? (a + 0.5f) : (1.f / (1.f + __expf(-a)));
    v = s * g;
}

// ---------------------------------------------------------------------------
// Kernel 0a: round x to fp16.
// ---------------------------------------------------------------------------
__global__ __launch_bounds__(256)
void split_x(const float* __restrict__ x)
{
    size_t i = ((size_t)blockIdx.x * 256 + threadIdx.x) * 4;
    float4 v = *reinterpret_cast<const float4*>(&x[i]);
    __half2 h0 = __halves2half2(__float2half_rn(v.x), __float2half_rn(v.y));
    __half2 h1 = __halves2half2(__float2half_rn(v.z), __float2half_rn(v.w));
    uint2 hu{*reinterpret_cast<uint32_t*>(&h0), *reinterpret_cast<uint32_t*>(&h1)};
    *reinterpret_cast<uint2*>(&g_xh[i]) = hu;
}

// ---------------------------------------------------------------------------
// Kernel 0b: round Wz / Wh to fp16.
// ---------------------------------------------------------------------------
__global__ __launch_bounds__(256)
void split_w(const float* __restrict__ Wz, const float* __restrict__ Wh)
{
    size_t i = ((size_t)blockIdx.x * 256 + threadIdx.x) * 4;
    {
        float4 v = *reinterpret_cast<const float4*>(&Wz[i]);
        __half2 h0 = __halves2half2(__float2half_rn(v.x), __float2half_rn(v.y));
        __half2 h1 = __halves2half2(__float2half_rn(v.z), __float2half_rn(v.w));
        uint2 hu{*reinterpret_cast<uint32_t*>(&h0), *reinterpret_cast<uint32_t*>(&h1)};
        *reinterpret_cast<uint2*>(&g_wzh[i]) = hu;
    }
    {
        float4 v = *reinterpret_cast<const float4*>(&Wh[i]);
        __half2 h0 = __halves2half2(__float2half_rn(v.x), __float2half_rn(v.y));
        __half2 h1 = __halves2half2(__float2half_rn(v.z), __float2half_rn(v.w));
        uint2 hu{*reinterpret_cast<uint32_t*>(&h0), *reinterpret_cast<uint32_t*>(&h1)};
        *reinterpret_cast<uint2*>(&g_whh[i]) = hu;
    }
}

// ---------------------------------------------------------------------------
// cp.async one K-chunk (32) stage into smem buffer. 256 threads, 4 CP16 each.
// ---------------------------------------------------------------------------
__device__ __forceinline__ void copy_stage(uint32_t sa, int m0, int n0, int k0, int tid)
{
    // x: 128 rows x 64B = 512 x 16B -> 2 per thread
    #pragma unroll
    for (int i = 0; i < 2; i++) {
        int f = tid + i * 256;
        int row = f >> 2, c = f & 3;
        uint32_t d = sa + row * RS + c * 16;
        size_t   s = (size_t)(m0 + row) * D_ + k0 + c * 8;
        CP16(d + OX_H, &g_xh[s]);
    }
    // W: 64 rows x 64B = 256 x 16B per matrix -> 1 per thread per matrix
    {
        int row = tid >> 2, c = tid & 3;
        uint32_t d = sa + row * RS + c * 16;
        size_t   s = (size_t)(n0 + row) * D_ + k0 + c * 8;
        CP16(d + OW0H, &g_wzh[s]);
        CP16(d + OW1H, &g_whh[s]);
    }
}

// ---------------------------------------------------------------------------
// Kernel 1: dual-output fp16 mma.sync GEMM + fused gates + fused per-chunk
// scan summaries (two TC=64 chunks per CTA).
// ---------------------------------------------------------------------------
__global__ __launch_bounds__(256, 2)
void gemm_gate_mma(const float* __restrict__ bh, const float* __restrict__ bz)
{
    extern __shared__ char smem[];
    const int tid  = threadIdx.x;
    const int wid  = tid >> 5;
    const int lane = tid & 31;
    const int n0   = blockIdx.x * BN;
    const int m0   = blockIdx.y * BM;
    const int wm   = wid >> 1;          // 0..3 : 32-row tile
    const int wn   = wid & 1;           // 0..1 : 32-col tile

    float accK[32], accA[32];
    #pragma unroll
    for (int i = 0; i < 32; i++) { accK[i] = 0.f; accA[i] = 0.f; }

    const uint32_t sm0 = smem_u32(smem);
    // A ldmatrix lane address: row = wm*32 + (lane&15), +16B col for lane>=16
    const uint32_t aBase = sm0 + (uint32_t)(wm * 32 + (lane & 15)) * RS + (lane >> 4) * 16;
    // B ldmatrix lane address: nrow = wn*32 + (lane>>4)*8 + (lane&7)
    const uint32_t bBase = sm0 + (uint32_t)(wn * 32 + ((lane >> 4) << 3) + (lane & 7)) * RS
                           + ((lane >> 3) & 1) * 16;

    // Prime: 2 chunks in flight
    copy_stage(sm0, m0, n0, 0, tid);           CP_COMMIT();
    copy_stage(sm0 + SSTR, m0, n0, KCH, tid);  CP_COMMIT();

    for (int kc = 0; kc < NKC; kc++) {
        CP_WAIT(1);                 // chunk kc landed
        __syncthreads();            // also protects buffer (kc+2)%3 for rewrite
        if (kc + 2 < NKC)
            copy_stage(sm0 + (uint32_t)((kc + 2) % NSTAGE) * SSTR, m0, n0,
                       (kc + 2) * KCH, tid);
        CP_COMMIT();                // empty group when not copying keeps count uniform

        const uint32_t ss = (uint32_t)(kc % NSTAGE) * SSTR;
        #pragma unroll
        for (int kk = 0; kk < 2; kk++) {
            const uint32_t ko = kk * 32;
            uint32_t ah[2][4];
            #pragma unroll
            for (int ms = 0; ms < 2; ms++)
                ldsm_x4(ah[ms], aBase + ss + OX_H + ms * (16 * RS) + ko);
            uint32_t bzf[2][4], bhf[2][4];
            #pragma unroll
            for (int i = 0; i < 2; i++) {
                ldsm_x4(bzf[i], bBase + ss + OW0H + i * (16 * RS) + ko);
                ldsm_x4(bhf[i], bBase + ss + OW1H + i * (16 * RS) + ko);
            }
            #pragma unroll
            for (int ms = 0; ms < 2; ms++)
                #pragma unroll
                for (int ns = 0; ns < 4; ns++) {
                    const uint32_t* bz2 = &bzf[ns >> 1][(ns & 1) * 2];
                    const uint32_t* bh2 = &bhf[ns >> 1][(ns & 1) * 2];
                    mma_f16(accK + (ms * 4 + ns) * 4, ah[ms], bz2);   // x * Wz
                    mma_f16(accA + (ms * 4 + ns) * 4, ah[ms], bh2);   // x * Wh
                }
        }
    }

    // ---- epilogue: gates in-register; gmem half2 stores + smem staging ----
    __syncthreads();   // mainloop's last ldsm reads done before smem reuse
    uint32_t* Cs = reinterpret_cast<uint32_t*>(smem);   // [128][64] half2-as-u32

    #pragma unroll
    for (int ms = 0; ms < 2; ms++)
        #pragma unroll
        for (int ns = 0; ns < 4; ns++) {
            const int idx = (ms * 4 + ns) * 4;
            const int nl  = wn * 32 + ns * 8 + (lane & 3) * 2;
            const int ng  = n0 + nl;
            const int ml  = wm * 32 + ms * 16 + (lane >> 2);
            const float bz0 = bz[ng], bz1 = bz[ng + 1];
            const float bh0 = bh[ng], bh1 = bh[ng + 1];
            #pragma unroll
            for (int rh = 0; rh < 2; rh++) {
                const int t = ml + rh * 8;            // local row 0..127
                const int m = m0 + t;
                float c0, v0, c1, v1;
                gate(accK[idx + rh * 2 + 0] + bz0, accA[idx + rh * 2 + 0] + bh0, c0, v0);
                gate(accK[idx + rh * 2 + 1] + bz1, accA[idx + rh * 2 + 1] + bh1, c1, v1);
                __half2 cv0 = __halves2half2(__float2half_rn(c0), __float2half_rn(v0));
                __half2 cv1 = __halves2half2(__float2half_rn(c1), __float2half_rn(v1));
                uint2 w{*reinterpret_cast<uint32_t*>(&cv0),
                        *reinterpret_cast<uint32_t*>(&cv1)};
                *reinterpret_cast<uint2*>(&g_cv[(size_t)m * H_ + ng]) = w;
                *reinterpret_cast<uint2*>(&Cs[t * 64 + nl]) = w;
            }
        }
    __syncthreads();

    // ---- fused scan_pass1: 128 threads = 2 chunk-halves x 64 channels ----
    if (tid < 128) {
        const int half = tid >> 6;                    // 0,1 : which TC=64 half
        const int ch   = tid & 63;
        const uint32_t* base = Cs + half * (TC * 64) + ch;
        float A = 1.f, Bv = 0.f;
        #pragma unroll 8
        for (int t = 0; t < TC; t++) {
            uint32_t w = base[t * 64];
            float2 cv = __half22float2(*reinterpret_cast<__half2*>(&w));
            Bv = fmaf(cv.x, Bv, cv.y);
            A *= cv.x;
        }
        const int b     = m0 / T_;
        const int chunk = (m0 % T_) / TC + half;
        const int o = (b * NCHUNK + chunk) * H_ + n0 + ch;
        g_sumA[o] = A;
        g_sumB[o] = Bv;
    }
}

// ---------------------------------------------------------------------------
// Kernel 3: sequential combine over chunks -> carry-in per chunk.
// Batched loads (groups of 8, independent) hide the gmem latency chain.
// ---------------------------------------------------------------------------
__global__ void scan_pass2(const float* __restrict__ h_prev)
{
    const int h = threadIdx.x;
    const int b = blockIdx.x;
    float carry = h_prev[b * H_ + h];
    for (int jb = 0; jb < NCHUNK; jb += 8) {
        float As[8], Bs[8];
        #pragma unroll
        for (int u = 0; u < 8; u++) {
            int o = (b * NCHUNK + jb + u) * H_ + h;
            As[u] = g_sumA[o];
            Bs[u] = g_sumB[o];
        }
        #pragma unroll
        for (int u = 0; u < 8; u++) {
            int o = (b * NCHUNK + jb + u) * H_ + h;
            g_carry[o] = carry;
            carry = fmaf(As[u], carry, Bs[u]);
        }
    }
}

// ---------------------------------------------------------------------------
// Kernel 4: replay chunk scan with correct carry, write output.
// 128 threads, 4 channels each (uint4 loads, float4 stores).
// ---------------------------------------------------------------------------
__global__ void scan_pass3(float* __restrict__ out)
{
    const int h4    = threadIdx.x * 4;
    const int chunk = blockIdx.x;
    const int b     = blockIdx.y;
    const int co = (b * NCHUNK + chunk) * H_ + h4;
    float4 hc = *reinterpret_cast<const float4*>(&g_carry[co]);
    size_t base = ((size_t)(b * T_ + chunk * TC)) * H_ + h4;
    #pragma unroll 8
    for (int t = 0; t < TC; t++) {
        uint4 w = *reinterpret_cast<const uint4*>(&g_cv[base]);
        float2 cv0 = __half22float2(*reinterpret_cast<__half2*>(&w.x));
        float2 cv1 = __half22float2(*reinterpret_cast<__half2*>(&w.y));
        float2 cv2 = __half22float2(*reinterpret_cast<__half2*>(&w.z));
        float2 cv3 = __half22float2(*reinterpret_cast<__half2*>(&w.w));
        hc.x = fmaf(cv0.x, hc.x, cv0.y);
        hc.y = fmaf(cv1.x, hc.y, cv1.y);
        hc.z = fmaf(cv2.x, hc.z, cv2.y);
        hc.w = fmaf(cv3.x, hc.w, cv3.y);
        *reinterpret_cast<float4*>(&out[base]) = hc;
        base += H_;
    }
}

// ---------------------------------------------------------------------------
extern "C" void kernel_launch(void* const* d_in, const int* in_sizes, int n_in,
                              void* d_out, int out_size)
{
    const float* x      = (const float*)d_in[0];  // (B,T,D)
    const float* h_prev = (const float*)d_in[1];  // (B,1,H)
    const float* W_h    = (const float*)d_in[2];  // (H,D)
    const float* b_h    = (const float*)d_in[3];  // (H)
    const float* W_z    = (const float*)d_in[4];  // (H,D)
    const float* b_z    = (const float*)d_in[5];  // (H)
    float* out = (float*)d_out;                   // (B,T,H)

    cudaFuncSetAttribute(gemm_gate_mma, cudaFuncAttributeMaxDynamicSharedMemorySize, SMEM_BYTES);

    split_x<<<(M_ * D_) / (256 * 4), 256>>>(x);
    split_w<<<(H_ * D_) / (256 * 4), 256>>>(W_z, W_h);

    dim3 gemm_grid(H_ / BN, M_ / BM);             // (8, 256)
    gemm_gate_mma<<<gemm_grid, 256, SMEM_BYTES>>>(b_h, b_z);

    scan_pass2<<<B_, H_>>>(h_prev);
    scan_pass3<<<dim3(NCHUNK, B_), 128>>>(out);
}

// round 16
// speedup vs baseline: 1.0225x; 1.0225x over previous
#include <cuda_runtime.h>
#include <cuda_fp16.h>
#include <cstdint>

// Problem shapes (fixed by the dataset)
#define B_  4
#define T_  8192
#define D_  512
#define H_  512
#define M_  (B_ * T_)        // 32768 rows

#define NCHUNK 128
#define TC     (T_ / NCHUNK) // 64

// Scratch (device globals: allocation-free rule)
// Packed gates: g_cv[m*H+h] = half2{c, v}
__device__ __half2 g_cv[(size_t)M_ * H_];
__device__ float g_sumA[B_ * NCHUNK * H_];
__device__ float g_sumB[B_ * NCHUNK * H_];
__device__ float g_carry[B_ * NCHUNK * H_];

// fp16-rounded operands
__device__ __half g_xh[(size_t)M_ * D_];             // 32 MB
__device__ __half g_wzh[H_ * D_];
__device__ __half g_whh[H_ * D_];

// ---------------------------------------------------------------------------
// GEMM config: CTA tile M=128, N=64, K chunk 32, 8 dual-output warps,
// 3-stage cp.async pipeline (prefetch depth 2), one barrier per chunk.
// ---------------------------------------------------------------------------
#define BM 128
#define BN 64
#define KCH 32
#define NKC (D_ / KCH)       // 16
#define NSTAGE 3

// Row stride 80 = 64B data + 16B pad: multiple of 16 (cp.async/ldmatrix
// alignment); 80*r mod 128, r=0..7 -> {0,80,32,112,64,16,96,48}: conflict-free.
#define RS   80
#define OX_H 0                     // x  : 128 x 80
#define OW0H (OX_H + BM * RS)      // 10240  Wz : 64 x 80
#define OW1H (OW0H + BN * RS)      // 15360  Wh : 64 x 80
#define SSTR (OW1H + BN * RS)      // 20480
#define SMEM_BYTES (NSTAGE * SSTR) // 61440

__device__ __forceinline__ uint32_t smem_u32(const void* p) {
    uint32_t a;
    asm("{ .reg .u64 t; cvta.to.shared.u64 t, %1; cvt.u32.u64 %0, t; }"
        : "=r"(a) : "l"(p));
    return a;
}

#define CP16(dst, src) \
    asm volatile("cp.async.cg.shared.global [%0], [%1], 16;" :: "r"(dst), "l"(src))
#define CP_COMMIT() asm volatile("cp.async.commit_group;" ::: "memory")
#define CP_WAIT(n)  asm volatile("cp.async.wait_group %0;" :: "n"(n) : "memory")

__device__ __forceinline__ void ldsm_x4(uint32_t* r, uint32_t addr) {
    asm volatile("ldmatrix.sync.aligned.m8n8.x4.shared.b16 {%0,%1,%2,%3}, [%4];"
                 : "=r"(r[0]), "=r"(r[1]), "=r"(r[2]), "=r"(r[3]) : "r"(addr));
}

__device__ __forceinline__ void mma_f16(float* d, const uint32_t* a, const uint32_t* b) {
    asm volatile("mma.sync.aligned.m16n8k16.row.col.f32.f16.f16.f32 "
                 "{%0,%1,%2,%3}, {%4,%5,%6,%7}, {%8,%9}, {%0,%1,%2,%3};"
                 : "+f"(d[0]), "+f"(d[1]), "+f"(d[2]), "+f"(d[3])
                 : "r"(a[0]), "r"(a[1]), "r"(a[2]), "r"(a[3]), "r"(b[0]), "r"(b[1]));
}

__device__ __forceinline__ void gate(float k, float a, float& c, float& v) {
    c = 1.f / (1.f + __expf(k));                                 // sigmoid(-k)
    float s = 1.f / (1.f + __expf(-k));                          // sigmoid(k)
    float g = (a >= 0.f) ? (a + 0.5f) : (1.f / (1.f + __expf(-a)));
    v = s * g;
}

// ---------------------------------------------------------------------------
// Kernel 0a: round x to fp16.
// ---------------------------------------------------------------------------
__global__ __launch_bounds__(256)
void split_x(const float* __restrict__ x)
{
    size_t i = ((size_t)blockIdx.x * 256 + threadIdx.x) * 4;
    float4 v = *reinterpret_cast<const float4*>(&x[i]);
    __half2 h0 = __halves2half2(__float2half_rn(v.x), __float2half_rn(v.y));
    __half2 h1 = __halves2half2(__float2half_rn(v.z), __float2half_rn(v.w));
    uint2 hu{*reinterpret_cast<uint32_t*>(&h0), *reinterpret_cast<uint32_t*>(&h1)};
    *reinterpret_cast<uint2*>(&g_xh[i]) = hu;
}

// ---------------------------------------------------------------------------
// Kernel 0b: round Wz / Wh to fp16.
// ---------------------------------------------------------------------------
__global__ __launch_bounds__(256)
void split_w(const float* __restrict__ Wz, const float* __restrict__ Wh)
{
    size_t i = ((size_t)blockIdx.x * 256 + threadIdx.x) * 4;
    {
        float4 v = *reinterpret_cast<const float4*>(&Wz[i]);
        __half2 h0 = __halves2half2(__float2half_rn(v.x), __float2half_rn(v.y));
        __half2 h1 = __halves2half2(__float2half_rn(v.z), __float2half_rn(v.w));
        uint2 hu{*reinterpret_cast<uint32_t*>(&h0), *reinterpret_cast<uint32_t*>(&h1)};
        *reinterpret_cast<uint2*>(&g_wzh[i]) = hu;
    }
    {
        float4 v = *reinterpret_cast<const float4*>(&Wh[i]);
        __half2 h0 = __halves2half2(__float2half_rn(v.x), __float2half_rn(v.y));
        __half2 h1 = __halves2half2(__float2half_rn(v.z), __float2half_rn(v.w));
        uint2 hu{*reinterpret_cast<uint32_t*>(&h0), *reinterpret_cast<uint32_t*>(&h1)};
        *reinterpret_cast<uint2*>(&g_whh[i]) = hu;
    }
}

// ---------------------------------------------------------------------------
// cp.async one K-chunk (32) stage into smem buffer. 256 threads, 4 CP16 each.
// ---------------------------------------------------------------------------
__device__ __forceinline__ void copy_stage(uint32_t sa, int m0, int n0, int k0, int tid)
{
    // x: 128 rows x 64B = 512 x 16B -> 2 per thread
    #pragma unroll
    for (int i = 0; i < 2; i++) {
        int f = tid + i * 256;
        int row = f >> 2, c = f & 3;
        uint32_t d = sa + row * RS + c * 16;
        size_t   s = (size_t)(m0 + row) * D_ + k0 + c * 8;
        CP16(d + OX_H, &g_xh[s]);
    }
    // W: 64 rows x 64B = 256 x 16B per matrix -> 1 per thread per matrix
    {
        int row = tid >> 2, c = tid & 3;
        uint32_t d = sa + row * RS + c * 16;
        size_t   s = (size_t)(n0 + row) * D_ + k0 + c * 8;
        CP16(d + OW0H, &g_wzh[s]);
        CP16(d + OW1H, &g_whh[s]);
    }
}

// ---------------------------------------------------------------------------
// Kernel 1: dual-output fp16 mma.sync GEMM + fused gate epilogue.
//   8 warps, warp tile 32x32, each warp computes BOTH accK (x*Wz^T) and
//   accA (x*Wh^T); A fragments shared, epilogue fully in-register.
// ---------------------------------------------------------------------------
__global__ __launch_bounds__(256, 2)
void gemm_gate_mma(const float* __restrict__ bh, const float* __restrict__ bz)
{
    extern __shared__ char smem[];
    const int tid  = threadIdx.x;
    const int wid  = tid >> 5;
    const int lane = tid & 31;
    const int n0   = blockIdx.x * BN;
    const int m0   = blockIdx.y * BM;
    const int wm   = wid >> 1;          // 0..3 : 32-row tile
    const int wn   = wid & 1;           // 0..1 : 32-col tile

    float accK[32], accA[32];
    #pragma unroll
    for (int i = 0; i < 32; i++) { accK[i] = 0.f; accA[i] = 0.f; }

    const uint32_t sm0 = smem_u32(smem);
    // A ldmatrix lane address: row = wm*32 + (lane&15), +16B col for lane>=16
    const uint32_t aBase = sm0 + (uint32_t)(wm * 32 + (lane & 15)) * RS + (lane >> 4) * 16;
    // B ldmatrix lane address: nrow = wn*32 + (lane>>4)*8 + (lane&7)
    const uint32_t bBase = sm0 + (uint32_t)(wn * 32 + ((lane >> 4) << 3) + (lane & 7)) * RS
                           + ((lane >> 3) & 1) * 16;

    // Prime: 2 chunks in flight
    copy_stage(sm0, m0, n0, 0, tid);           CP_COMMIT();
    copy_stage(sm0 + SSTR, m0, n0, KCH, tid);  CP_COMMIT();

    for (int kc = 0; kc < NKC; kc++) {
        CP_WAIT(1);                 // chunk kc landed
        __syncthreads();            // also protects buffer (kc+2)%3 for rewrite
        if (kc + 2 < NKC)
            copy_stage(sm0 + (uint32_t)((kc + 2) % NSTAGE) * SSTR, m0, n0,
                       (kc + 2) * KCH, tid);
        CP_COMMIT();                // empty group when not copying keeps count uniform

        const uint32_t ss = (uint32_t)(kc % NSTAGE) * SSTR;
        #pragma unroll
        for (int kk = 0; kk < 2; kk++) {
            const uint32_t ko = kk * 32;
            uint32_t ah[2][4];
            #pragma unroll
            for (int ms = 0; ms < 2; ms++)
                ldsm_x4(ah[ms], aBase + ss + OX_H + ms * (16 * RS) + ko);
            uint32_t bzf[2][4], bhf[2][4];
            #pragma unroll
            for (int i = 0; i < 2; i++) {
                ldsm_x4(bzf[i], bBase + ss + OW0H + i * (16 * RS) + ko);
                ldsm_x4(bhf[i], bBase + ss + OW1H + i * (16 * RS) + ko);
            }
            #pragma unroll
            for (int ms = 0; ms < 2; ms++)
                #pragma unroll
                for (int ns = 0; ns < 4; ns++) {
                    const uint32_t* bz2 = &bzf[ns >> 1][(ns & 1) * 2];
                    const uint32_t* bh2 = &bhf[ns >> 1][(ns & 1) * 2];
                    mma_f16(accK + (ms * 4 + ns) * 4, ah[ms], bz2);   // x * Wz
                    mma_f16(accA + (ms * 4 + ns) * 4, ah[ms], bh2);   // x * Wh
                }
        }
    }

    // ---- epilogue: gates in-register, packed half2{c,v} stores ----
    #pragma unroll
    for (int ms = 0; ms < 2; ms++)
        #pragma unroll
        for (int ns = 0; ns < 4; ns++) {
            const int idx = (ms * 4 + ns) * 4;
            const int nl  = wn * 32 + ns * 8 + (lane & 3) * 2;
            const int ng  = n0 + nl;
            const int ml  = wm * 32 + ms * 16 + (lane >> 2);
            const float bz0 = bz[ng], bz1 = bz[ng + 1];
            const float bh0 = bh[ng], bh1 = bh[ng + 1];
            #pragma unroll
            for (int rh = 0; rh < 2; rh++) {
                const int m = m0 + ml + rh * 8;
                float c0, v0, c1, v1;
                gate(accK[idx + rh * 2 + 0] + bz0, accA[idx + rh * 2 + 0] + bh0, c0, v0);
                gate(accK[idx + rh * 2 + 1] + bz1, accA[idx + rh * 2 + 1] + bh1, c1, v1);
                __half2 cv0 = __halves2half2(__float2half_rn(c0), __float2half_rn(v0));
                __half2 cv1 = __halves2half2(__float2half_rn(c1), __float2half_rn(v1));
                uint2 w{*reinterpret_cast<uint32_t*>(&cv0),
                        *reinterpret_cast<uint32_t*>(&cv1)};
                *reinterpret_cast<uint2*>(&g_cv[(size_t)m * H_ + ng]) = w;
            }
        }
}

// ---------------------------------------------------------------------------
// Kernel 2: per-chunk affine summaries. 256 threads, 2 channels each (uint2).
// ---------------------------------------------------------------------------
__global__ void scan_pass1()
{
    const int h2    = threadIdx.x * 2;
    const int chunk = blockIdx.x;
    const int b     = blockIdx.y;
    size_t base = ((size_t)(b * T_ + chunk * TC)) * H_ + h2;
    float A0 = 1.f, B0 = 0.f, A1 = 1.f, B1 = 0.f;
    #pragma unroll 8
    for (int t = 0; t < TC; t++) {
        uint2 w = *reinterpret_cast<const uint2*>(&g_cv[base]);
        float2 cv0 = __half22float2(*reinterpret_cast<__half2*>(&w.x));
        float2 cv1 = __half22float2(*reinterpret_cast<__half2*>(&w.y));
        B0 = fmaf(cv0.x, B0, cv0.y);  A0 *= cv0.x;
        B1 = fmaf(cv1.x, B1, cv1.y);  A1 *= cv1.x;
        base += H_;
    }
    int o = (b * NCHUNK + chunk) * H_ + h2;
    g_sumA[o] = A0;  g_sumA[o + 1] = A1;
    g_sumB[o] = B0;  g_sumB[o + 1] = B1;
}

// ---------------------------------------------------------------------------
// Kernel 3: sequential combine over chunks -> carry-in per chunk.
// Batch-16 loads (independent) halve the serial latency rounds.
// ---------------------------------------------------------------------------
__global__ void scan_pass2(const float* __restrict__ h_prev)
{
    const int h = threadIdx.x;
    const int b = blockIdx.x;
    float carry = h_prev[b * H_ + h];
    for (int jb = 0; jb < NCHUNK; jb += 16) {
        float As[16], Bs[16];
        #pragma unroll
        for (int u = 0; u < 16; u++) {
            int o = (b * NCHUNK + jb + u) * H_ + h;
            As[u] = g_sumA[o];
            Bs[u] = g_sumB[o];
        }
        #pragma unroll
        for (int u = 0; u < 16; u++) {
            int o = (b * NCHUNK + jb + u) * H_ + h;
            g_carry[o] = carry;
            carry = fmaf(As[u], carry, Bs[u]);
        }
    }
}

// ---------------------------------------------------------------------------
// Kernel 4: replay chunk scan with correct carry, write output.
// 128 threads, 4 channels each (uint4 loads, float4 stores).
// ---------------------------------------------------------------------------
__global__ void scan_pass3(float* __restrict__ out)
{
    const int h4    = threadIdx.x * 4;
    const int chunk = blockIdx.x;
    const int b     = blockIdx.y;
    const int co = (b * NCHUNK + chunk) * H_ + h4;
    float4 hc = *reinterpret_cast<const float4*>(&g_carry[co]);
    size_t base = ((size_t)(b * T_ + chunk * TC)) * H_ + h4;
    #pragma unroll 8
    for (int t = 0; t < TC; t++) {
        uint4 w = *reinterpret_cast<const uint4*>(&g_cv[base]);
        float2 cv0 = __half22float2(*reinterpret_cast<__half2*>(&w.x));
        float2 cv1 = __half22float2(*reinterpret_cast<__half2*>(&w.y));
        float2 cv2 = __half22float2(*reinterpret_cast<__half2*>(&w.z));
        float2 cv3 = __half22float2(*reinterpret_cast<__half2*>(&w.w));
        hc.x = fmaf(cv0.x, hc.x, cv0.y);
        hc.y = fmaf(cv1.x, hc.y, cv1.y);
        hc.z = fmaf(cv2.x, hc.z, cv2.y);
        hc.w = fmaf(cv3.x, hc.w, cv3.y);
        *reinterpret_cast<float4*>(&out[base]) = hc;
        base += H_;
    }
}

// ---------------------------------------------------------------------------
extern "C" void kernel_launch(void* const* d_in, const int* in_sizes, int n_in,
                              void* d_out, int out_size)
{
    const float* x      = (const float*)d_in[0];  // (B,T,D)
    const float* h_prev = (const float*)d_in[1];  // (B,1,H)
    const float* W_h    = (const float*)d_in[2];  // (H,D)
    const float* b_h    = (const float*)d_in[3];  // (H)
    const float* W_z    = (const float*)d_in[4];  // (H,D)
    const float* b_z    = (const float*)d_in[5];  // (H)
    float* out = (float*)d_out;                   // (B,T,H)

    cudaFuncSetAttribute(gemm_gate_mma, cudaFuncAttributeMaxDynamicSharedMemorySize, SMEM_BYTES);

    split_x<<<(M_ * D_) / (256 * 4), 256>>>(x);
    split_w<<<(H_ * D_) / (256 * 4), 256>>>(W_z, W_h);

    dim3 gemm_grid(H_ / BN, M_ / BM);             // (8, 256)
    gemm_gate_mma<<<gemm_grid, 256, SMEM_BYTES>>>(b_h, b_z);

    scan_pass1<<<dim3(NCHUNK, B_), 256>>>();
    scan_pass2<<<B_, H_>>>(h_prev);
    scan_pass3<<<dim3(NCHUNK, B_), 128>>>(out);
}

// round 17
// speedup vs baseline: 1.0603x; 1.0369x over previous
#include <cuda_runtime.h>
#include <cuda_fp16.h>
#include <cstdint>

// Problem shapes (fixed by the dataset)
#define B_  4
#define T_  8192
#define D_  512
#define H_  512
#define M_  (B_ * T_)        // 32768 rows

#define NCHUNK 128
#define TC     (T_ / NCHUNK) // 64

// Scratch (device globals: allocation-free rule)
// Packed gates: g_cv[m*H+h] = half2{c, v}
__device__ __half2 g_cv[(size_t)M_ * H_];
__device__ float g_sumA[B_ * NCHUNK * H_];
__device__ float g_sumB[B_ * NCHUNK * H_];
__device__ float g_carry[B_ * NCHUNK * H_];

// fp16-rounded operands
__device__ __half g_xh[(size_t)M_ * D_];             // 32 MB
__device__ __half g_wzh[H_ * D_];
__device__ __half g_whh[H_ * D_];

// ---------------------------------------------------------------------------
// GEMM config: CTA tile M=128, N=64, K chunk 32, 8 dual-output warps,
// 3-stage cp.async pipeline (prefetch depth 2), one barrier per chunk.
// ---------------------------------------------------------------------------
#define BM 128
#define BN 64
#define KCH 32
#define NKC (D_ / KCH)       // 16
#define NSTAGE 3

// Row stride 80 = 64B data + 16B pad: multiple of 16 (cp.async/ldmatrix
// alignment); 80*r mod 128, r=0..7 -> {0,80,32,112,64,16,96,48}: conflict-free.
#define RS   80
#define OX_H 0                     // x  : 128 x 80
#define OW0H (OX_H + BM * RS)      // 10240  Wz : 64 x 80
#define OW1H (OW0H + BN * RS)      // 15360  Wh : 64 x 80
#define SSTR (OW1H + BN * RS)      // 20480
#define SMEM_BYTES (NSTAGE * SSTR) // 61440

__device__ __forceinline__ uint32_t smem_u32(const void* p) {
    uint32_t a;
    asm("{ .reg .u64 t; cvta.to.shared.u64 t, %1; cvt.u32.u64 %0, t; }"
        : "=r"(a) : "l"(p));
    return a;
}

#define CP16(dst, src) \
    asm volatile("cp.async.cg.shared.global [%0], [%1], 16;" :: "r"(dst), "l"(src))
#define CP_COMMIT() asm volatile("cp.async.commit_group;" ::: "memory")
#define CP_WAIT(n)  asm volatile("cp.async.wait_group %0;" :: "n"(n) : "memory")

__device__ __forceinline__ void ldsm_x4(uint32_t* r, uint32_t addr) {
    asm volatile("ldmatrix.sync.aligned.m8n8.x4.shared.b16 {%0,%1,%2,%3}, [%4];"
                 : "=r"(r[0]), "=r"(r[1]), "=r"(r[2]), "=r"(r[3]) : "r"(addr));
}

__device__ __forceinline__ void mma_f16(float* d, const uint32_t* a, const uint32_t* b) {
    asm volatile("mma.sync.aligned.m16n8k16.row.col.f32.f16.f16.f32 "
                 "{%0,%1,%2,%3}, {%4,%5,%6,%7}, {%8,%9}, {%0,%1,%2,%3};"
                 : "+f"(d[0]), "+f"(d[1]), "+f"(d[2]), "+f"(d[3])
                 : "r"(a[0]), "r"(a[1]), "r"(a[2]), "r"(a[3]), "r"(b[0]), "r"(b[1]));
}

__device__ __forceinline__ void gate(float k, float a, float& c, float& v) {
    c = 1.f / (1.f + __expf(k));                                 // sigmoid(-k)
    float s = 1.f / (1.f + __expf(-k));                          // sigmoid(k)
    float g = (a >= 0.f) ? (a + 0.5f) : (1.f / (1.f + __expf(-a)));
    v = s * g;
}

// ---------------------------------------------------------------------------
// Kernel 0: round x, Wz, Wh to fp16 (single launch, blockIdx-partitioned).
// ---------------------------------------------------------------------------
#define XBLK ((M_ * D_) / (256 * 4))      // 16384 blocks for x
#define WBLK ((H_ * D_) / (256 * 4))      // 256 blocks for W

__global__ __launch_bounds__(256)
void split_xw(const float* __restrict__ x,
              const float* __restrict__ Wz, const float* __restrict__ Wh)
{
    if (blockIdx.x < XBLK) {
        size_t i = ((size_t)blockIdx.x * 256 + threadIdx.x) * 4;
        float4 v = *reinterpret_cast<const float4*>(&x[i]);
        __half2 h0 = __halves2half2(__float2half_rn(v.x), __float2half_rn(v.y));
        __half2 h1 = __halves2half2(__float2half_rn(v.z), __float2half_rn(v.w));
        uint2 hu{*reinterpret_cast<uint32_t*>(&h0), *reinterpret_cast<uint32_t*>(&h1)};
        *reinterpret_cast<uint2*>(&g_xh[i]) = hu;
    } else {
        size_t i = ((size_t)(blockIdx.x - XBLK) * 256 + threadIdx.x) * 4;
        {
            float4 v = *reinterpret_cast<const float4*>(&Wz[i]);
            __half2 h0 = __halves2half2(__float2half_rn(v.x), __float2half_rn(v.y));
            __half2 h1 = __halves2half2(__float2half_rn(v.z), __float2half_rn(v.w));
            uint2 hu{*reinterpret_cast<uint32_t*>(&h0), *reinterpret_cast<uint32_t*>(&h1)};
            *reinterpret_cast<uint2*>(&g_wzh[i]) = hu;
        }
        {
            float4 v = *reinterpret_cast<const float4*>(&Wh[i]);
            __half2 h0 = __halves2half2(__float2half_rn(v.x), __float2half_rn(v.y));
            __half2 h1 = __halves2half2(__float2half_rn(v.z), __float2half_rn(v.w));
            uint2 hu{*reinterpret_cast<uint32_t*>(&h0), *reinterpret_cast<uint32_t*>(&h1)};
            *reinterpret_cast<uint2*>(&g_whh[i]) = hu;
        }
    }
}

// ---------------------------------------------------------------------------
// cp.async one K-chunk (32) stage into smem buffer. 256 threads, 4 CP16 each.
// ---------------------------------------------------------------------------
__device__ __forceinline__ void copy_stage(uint32_t sa, int m0, int n0, int k0, int tid)
{
    // x: 128 rows x 64B = 512 x 16B -> 2 per thread
    #pragma unroll
    for (int i = 0; i < 2; i++) {
        int f = tid + i * 256;
        int row = f >> 2, c = f & 3;
        uint32_t d = sa + row * RS + c * 16;
        size_t   s = (size_t)(m0 + row) * D_ + k0 + c * 8;
        CP16(d + OX_H, &g_xh[s]);
    }
    // W: 64 rows x 64B = 256 x 16B per matrix -> 1 per thread per matrix
    {
        int row = tid >> 2, c = tid & 3;
        uint32_t d = sa + row * RS + c * 16;
        size_t   s = (size_t)(n0 + row) * D_ + k0 + c * 8;
        CP16(d + OW0H, &g_wzh[s]);
        CP16(d + OW1H, &g_whh[s]);
    }
}

// ---------------------------------------------------------------------------
// Kernel 1: dual-output fp16 mma.sync GEMM + fused gate epilogue.
//   8 warps, warp tile 32x32, each warp computes BOTH accK (x*Wz^T) and
//   accA (x*Wh^T); A fragments shared, epilogue fully in-register.
// ---------------------------------------------------------------------------
__global__ __launch_bounds__(256, 2)
void gemm_gate_mma(const float* __restrict__ bh, const float* __restrict__ bz)
{
    extern __shared__ char smem[];
    const int tid  = threadIdx.x;
    const int wid  = tid >> 5;
    const int lane = tid & 31;
    const int n0   = blockIdx.x * BN;
    const int m0   = blockIdx.y * BM;
    const int wm   = wid >> 1;          // 0..3 : 32-row tile
    const int wn   = wid & 1;           // 0..1 : 32-col tile

    float accK[32], accA[32];
    #pragma unroll
    for (int i = 0; i < 32; i++) { accK[i] = 0.f; accA[i] = 0.f; }

    const uint32_t sm0 = smem_u32(smem);
    // A ldmatrix lane address: row = wm*32 + (lane&15), +16B col for lane>=16
    const uint32_t aBase = sm0 + (uint32_t)(wm * 32 + (lane & 15)) * RS + (lane >> 4) * 16;
    // B ldmatrix lane address: nrow = wn*32 + (lane>>4)*8 + (lane&7)
    const uint32_t bBase = sm0 + (uint32_t)(wn * 32 + ((lane >> 4) << 3) + (lane & 7)) * RS
                           + ((lane >> 3) & 1) * 16;

    // Prime: 2 chunks in flight
    copy_stage(sm0, m0, n0, 0, tid);           CP_COMMIT();
    copy_stage(sm0 + SSTR, m0, n0, KCH, tid);  CP_COMMIT();

    for (int kc = 0; kc < NKC; kc++) {
        CP_WAIT(1);                 // chunk kc landed
        __syncthreads();            // also protects buffer (kc+2)%3 for rewrite
        if (kc + 2 < NKC)
            copy_stage(sm0 + (uint32_t)((kc + 2) % NSTAGE) * SSTR, m0, n0,
                       (kc + 2) * KCH, tid);
        CP_COMMIT();                // empty group when not copying keeps count uniform

        const uint32_t ss = (uint32_t)(kc % NSTAGE) * SSTR;
        #pragma unroll
        for (int kk = 0; kk < 2; kk++) {
            const uint32_t ko = kk * 32;
            uint32_t ah[2][4];
            #pragma unroll
            for (int ms = 0; ms < 2; ms++)
                ldsm_x4(ah[ms], aBase + ss + OX_H + ms * (16 * RS) + ko);
            uint32_t bzf[2][4], bhf[2][4];
            #pragma unroll
            for (int i = 0; i < 2; i++) {
                ldsm_x4(bzf[i], bBase + ss + OW0H + i * (16 * RS) + ko);
                ldsm_x4(bhf[i], bBase + ss + OW1H + i * (16 * RS) + ko);
            }
            #pragma unroll
            for (int ms = 0; ms < 2; ms++)
                #pragma unroll
                for (int ns = 0; ns < 4; ns++) {
                    const uint32_t* bz2 = &bzf[ns >> 1][(ns & 1) * 2];
                    const uint32_t* bh2 = &bhf[ns >> 1][(ns & 1) * 2];
                    mma_f16(accK + (ms * 4 + ns) * 4, ah[ms], bz2);   // x * Wz
                    mma_f16(accA + (ms * 4 + ns) * 4, ah[ms], bh2);   // x * Wh
                }
        }
    }

    // ---- epilogue: gates in-register, packed half2{c,v} stores ----
    #pragma unroll
    for (int ms = 0; ms < 2; ms++)
        #pragma unroll
        for (int ns = 0; ns < 4; ns++) {
            const int idx = (ms * 4 + ns) * 4;
            const int nl  = wn * 32 + ns * 8 + (lane & 3) * 2;
            const int ng  = n0 + nl;
            const int ml  = wm * 32 + ms * 16 + (lane >> 2);
            const float bz0 = bz[ng], bz1 = bz[ng + 1];
            const float bh0 = bh[ng], bh1 = bh[ng + 1];
            #pragma unroll
            for (int rh = 0; rh < 2; rh++) {
                const int m = m0 + ml + rh * 8;
                float c0, v0, c1, v1;
                gate(accK[idx + rh * 2 + 0] + bz0, accA[idx + rh * 2 + 0] + bh0, c0, v0);
                gate(accK[idx + rh * 2 + 1] + bz1, accA[idx + rh * 2 + 1] + bh1, c1, v1);
                __half2 cv0 = __halves2half2(__float2half_rn(c0), __float2half_rn(v0));
                __half2 cv1 = __halves2half2(__float2half_rn(c1), __float2half_rn(v1));
                uint2 w{*reinterpret_cast<uint32_t*>(&cv0),
                        *reinterpret_cast<uint32_t*>(&cv1)};
                *reinterpret_cast<uint2*>(&g_cv[(size_t)m * H_ + ng]) = w;
            }
        }
}

// ---------------------------------------------------------------------------
// Kernel 2: per-chunk affine summaries. 256 threads, 2 channels each (uint2).
// ---------------------------------------------------------------------------
__global__ void scan_pass1()
{
    const int h2    = threadIdx.x * 2;
    const int chunk = blockIdx.x;
    const int b     = blockIdx.y;
    size_t base = ((size_t)(b * T_ + chunk * TC)) * H_ + h2;
    float A0 = 1.f, B0 = 0.f, A1 = 1.f, B1 = 0.f;
    #pragma unroll 8
    for (int t = 0; t < TC; t++) {
        uint2 w = *reinterpret_cast<const uint2*>(&g_cv[base]);
        float2 cv0 = __half22float2(*reinterpret_cast<__half2*>(&w.x));
        float2 cv1 = __half22float2(*reinterpret_cast<__half2*>(&w.y));
        B0 = fmaf(cv0.x, B0, cv0.y);  A0 *= cv0.x;
        B1 = fmaf(cv1.x, B1, cv1.y);  A1 *= cv1.x;
        base += H_;
    }
    int o = (b * NCHUNK + chunk) * H_ + h2;
    g_sumA[o] = A0;  g_sumA[o + 1] = A1;
    g_sumB[o] = B0;  g_sumB[o + 1] = B1;
}

// ---------------------------------------------------------------------------
// Kernel 3: warp-parallel affine scan over chunks -> carry-in per chunk.
// One warp per (b,h) channel: lane l aggregates chunks [4l,4l+4), shfl-scan
// composes lane aggregates, exclusive shift, then per-lane replay.
// ---------------------------------------------------------------------------
__global__ __launch_bounds__(256)
void scan_pass2(const float* __restrict__ h_prev)
{
    const int gwarp = (blockIdx.x * 256 + threadIdx.x) >> 5;   // 0..2047
    const int lane  = threadIdx.x & 31;
    const int b = gwarp >> 9;          // / 512
    const int h = gwarp & 511;

    float a4[4], b4[4];
    #pragma unroll
    for (int u = 0; u < 4; u++) {
        int o = (b * NCHUNK + lane * 4 + u) * H_ + h;
        a4[u] = g_sumA[o];
        b4[u] = g_sumB[o];
    }
    // lane-local aggregate (chunks applied in order)
    float A = a4[0], Bv = b4[0];
    #pragma unroll
    for (int u = 1; u < 4; u++) {
        Bv = fmaf(a4[u], Bv, b4[u]);
        A  = A * a4[u];
    }
    // inclusive shfl scan: compose earlier-lane aggregates before ours
    float sA = A, sB = Bv;
    #pragma unroll
    for (int d = 1; d < 32; d <<= 1) {
        float pA = __shfl_up_sync(0xffffffffu, sA, d);
        float pB = __shfl_up_sync(0xffffffffu, sB, d);
        if (lane >= d) {
            sB = fmaf(sA, pB, sB);   // (prev then cur): B = A_cur*B_prev + B_cur
            sA = sA * pA;
        }
    }
    // exclusive prefix
    float eA = __shfl_up_sync(0xffffffffu, sA, 1);
    float eB = __shfl_up_sync(0xffffffffu, sB, 1);
    if (lane == 0) { eA = 1.f; eB = 0.f; }
    // carry entering this lane's first chunk, then replay
    float carry = fmaf(eA, h_prev[b * H_ + h], eB);
    #pragma unroll
    for (int u = 0; u < 4; u++) {
        int o = (b * NCHUNK + lane * 4 + u) * H_ + h;
        g_carry[o] = carry;
        carry = fmaf(a4[u], carry, b4[u]);
    }
}

// ---------------------------------------------------------------------------
// Kernel 4: replay chunk scan with correct carry, write output.
// 128 threads, 4 channels each (uint4 loads, float4 stores).
// ---------------------------------------------------------------------------
__global__ void scan_pass3(float* __restrict__ out)
{
    const int h4    = threadIdx.x * 4;
    const int chunk = blockIdx.x;
    const int b     = blockIdx.y;
    const int co = (b * NCHUNK + chunk) * H_ + h4;
    float4 hc = *reinterpret_cast<const float4*>(&g_carry[co]);
    size_t base = ((size_t)(b * T_ + chunk * TC)) * H_ + h4;
    #pragma unroll 8
    for (int t = 0; t < TC; t++) {
        uint4 w = *reinterpret_cast<const uint4*>(&g_cv[base]);
        float2 cv0 = __half22float2(*reinterpret_cast<__half2*>(&w.x));
        float2 cv1 = __half22float2(*reinterpret_cast<__half2*>(&w.y));
        float2 cv2 = __half22float2(*reinterpret_cast<__half2*>(&w.z));
        float2 cv3 = __half22float2(*reinterpret_cast<__half2*>(&w.w));
        hc.x = fmaf(cv0.x, hc.x, cv0.y);
        hc.y = fmaf(cv1.x, hc.y, cv1.y);
        hc.z = fmaf(cv2.x, hc.z, cv2.y);
        hc.w = fmaf(cv3.x, hc.w, cv3.y);
        *reinterpret_cast<float4*>(&out[base]) = hc;
        base += H_;
    }
}

// ---------------------------------------------------------------------------
extern "C" void kernel_launch(void* const* d_in, const int* in_sizes, int n_in,
                              void* d_out, int out_size)
{
    const float* x      = (const float*)d_in[0];  // (B,T,D)
    const float* h_prev = (const float*)d_in[1];  // (B,1,H)
    const float* W_h    = (const float*)d_in[2];  // (H,D)
    const float* b_h    = (const float*)d_in[3];  // (H)
    const float* W_z    = (const float*)d_in[4];  // (H,D)
    const float* b_z    = (const float*)d_in[5];  // (H)
    float* out = (float*)d_out;                   // (B,T,H)

    cudaFuncSetAttribute(gemm_gate_mma, cudaFuncAttributeMaxDynamicSharedMemorySize, SMEM_BYTES);

    split_xw<<<XBLK + WBLK, 256>>>(x, W_z, W_h);

    dim3 gemm_grid(H_ / BN, M_ / BM);             // (8, 256)
    gemm_gate_mma<<<gemm_grid, 256, SMEM_BYTES>>>(b_h, b_z);

    scan_pass1<<<dim3(NCHUNK, B_), 256>>>();
    scan_pass2<<<(B_ * H_ * 32) / 256, 256>>>(h_prev);   // 256 blocks
    scan_pass3<<<dim3(NCHUNK, B_), 128>>>(out);
}